// round 5
// baseline (speedup 1.0000x reference)
#include <cuda_runtime.h>
#include <cuda_bf16.h>

// AdderVDSR collapses analytically (established R0-R2, rel_err 1.2e-7):
//   relu(adder_conv) == 0 exactly after block 1, so all 16 adder blocks emit
//   zeros and  out[b,c] = out_b[c] + pixel_shuffle(conv3x3(x,up_w)+up_b, 2).
//
// R5: one thread = 4 conv cols x 2 channels = 16 output floats (2x STG.128).
//   - inputs: per (cin,row) slice cols j0-1..j0+4 = LDG.128 + 2 scalars
//   - weights: 54 contiguous floats for the channel pair -> 27x LDG.64,
//     register-resident (128-thread CTAs leave ~2x the reg budget of R4,
//     where ptxas at 32 regs re-materialized every weight load in-loop).

__global__ __launch_bounds__(128) void adder_vdsr_collapsed(
    const float* __restrict__ x,      // [2,3,128,128]
    const float* __restrict__ up_w,   // [12,3,3,3]
    const float* __restrict__ up_b,   // [12]
    const float* __restrict__ out_b,  // [3]
    float* __restrict__ out)          // [2,3,256,256]
{
    const int tx = threadIdx.x;                 // 0..31 -> conv cols 4tx..4tx+3
    const int ty = threadIdx.y;                 // 0..3
    const int i  = blockIdx.y * 4 + ty;         // conv row 0..127
    const int z  = blockIdx.z;                  // 0..11
    const int b  = z / 6;
    const int cp = z - 6 * b;
    const int c  = cp >> 1;
    const int p  = cp & 1;
    const int o0 = 4 * c + 2 * p;
    const int j0 = 4 * tx;

    // 54 CTA-uniform weights (channels o0, o0+1 contiguous) via 27x LDG.64.
    float wbuf[54];
    {
        const float2* Wv = reinterpret_cast<const float2*>(up_w + o0 * 27);
        #pragma unroll
        for (int k = 0; k < 27; k++) {
            float2 t = __ldg(Wv + k);
            wbuf[2 * k]     = t.x;
            wbuf[2 * k + 1] = t.y;
        }
    }
    const float bias0 = __ldg(up_b + o0);
    const float bias1 = __ldg(up_b + o0 + 1);
    const float ob    = __ldg(out_b + c);

    float a0[4], a1[4];               // channel o0 / o0+1, cols j0..j0+3
    #pragma unroll
    for (int q = 0; q < 4; q++) { a0[q] = bias0; a1[q] = bias1; }

    #pragma unroll
    for (int cin = 0; cin < 3; cin++) {
        const float* xp = x + (size_t)(b * 3 + cin) * 128 * 128;
        #pragma unroll
        for (int ki = 0; ki < 3; ki++) {
            const int gi = i - 1 + ki;
            const bool rok = (gi >= 0) & (gi < 128);
            const float* rowp = xp + gi * 128;

            float v[6];
            if (rok) {
                v[0] = (tx > 0)  ? __ldg(rowp + j0 - 1) : 0.0f;
                float4 m = __ldg(reinterpret_cast<const float4*>(rowp + j0));
                v[1] = m.x; v[2] = m.y; v[3] = m.z; v[4] = m.w;
                v[5] = (tx < 31) ? __ldg(rowp + j0 + 4) : 0.0f;
            } else {
                #pragma unroll
                for (int q = 0; q < 6; q++) v[q] = 0.0f;
            }

            #pragma unroll
            for (int kj = 0; kj < 3; kj++) {
                const float w0 = wbuf[cin * 9 + ki * 3 + kj];       // ch o0
                const float w1 = wbuf[27 + cin * 9 + ki * 3 + kj];  // ch o0+1
                #pragma unroll
                for (int q = 0; q < 4; q++) {
                    a0[q] = fmaf(v[q + kj], w0, a0[q]);
                    a1[q] = fmaf(v[q + kj], w1, a1[q]);
                }
            }
        }
    }

    // Pixel shuffle: conv col j -> out cols {2j, 2j+1} carry ch {o0, o0+1}.
    // Thread covers out cols 8tx..8tx+7 of row (2i+p): two float4 stores.
    float* row = out + ((size_t)(b * 3 + c) * 256 + (2 * i + p)) * 256;
    float4* row4 = reinterpret_cast<float4*>(row);
    row4[2 * tx]     = make_float4(a0[0] + ob, a1[0] + ob, a0[1] + ob, a1[1] + ob);
    row4[2 * tx + 1] = make_float4(a0[2] + ob, a1[2] + ob, a0[3] + ob, a1[3] + ob);
}

extern "C" void kernel_launch(void* const* d_in, const int* in_sizes, int n_in,
                              void* d_out, int out_size) {
    (void)in_sizes; (void)n_in; (void)out_size;
    const float* x     = (const float*)d_in[0];
    const float* up_w  = (const float*)d_in[1];
    const float* up_b  = (const float*)d_in[2];
    const float* out_b = (const float*)d_in[7];
    float* out = (float*)d_out;

    dim3 grid(1, 32, 12);   // 384 CTAs: y = conv-row/4, z = b*6 + c*2 + p
    dim3 block(32, 4);      // 128 threads
    adder_vdsr_collapsed<<<grid, block>>>(x, up_w, up_b, out_b, out);
}